// round 1
// baseline (speedup 1.0000x reference)
#include <cuda_runtime.h>

#define NU 50000
#define NI 50000
#define DD 64
#define HH 128
#define EE 500000
#define ZSZ (NU*DD)   // 3,200,000 floats per z-plane

// Scratch (static device allocations; ~103 MB total)
__device__ float g_z[(size_t)8*ZSZ]; // 0:zu0 1:zu1 2:zi0 3:zi1 4:hu0 5:hu1 6:hi0 7:hi1
__device__ float g_s[NU];
__device__ float g_el[NU];
__device__ float g_er[NU];
__device__ float g_no[NU];
__device__ float g_ni[NU];
__device__ float g_wsum[8];
__device__ float g_beta[8];

// ---------------------------------------------------------------- zero utils
__global__ void zero_zbuf_k(int zidx) {
    int t = blockIdx.x * blockDim.x + threadIdx.x;
    if (t < ZSZ/4)
        ((float4*)(g_z + (size_t)zidx * ZSZ))[t] = make_float4(0.f, 0.f, 0.f, 0.f);
}

__global__ void zero_nodes_k() {
    int t = blockIdx.x * blockDim.x + threadIdx.x;
    if (t < NU) { g_s[t] = 0.f; g_no[t] = 0.f; g_ni[t] = 0.f; }
    if (t < 8) g_wsum[t] = 0.f;
}

// ------------------------------------------------------- GAT: el/er (GEMV-64)
__global__ void ler_k(const float* __restrict__ fsrc, const float* __restrict__ fdst,
                      const float* __restrict__ al, const float* __restrict__ ar) {
    int w    = (blockIdx.x * blockDim.x + threadIdx.x) >> 5;
    int lane = threadIdx.x & 31;
    const float* f; const float* a; float* out;
    if (w < NU) {
        f = fsrc + (size_t)w * DD; a = al; out = g_el + w;
    } else {
        int node = w - NU;
        if (node >= NU) return;
        f = fdst + (size_t)node * DD; a = ar; out = g_er + node;
    }
    float s = f[lane] * a[lane] + f[lane + 32] * a[lane + 32];
    #pragma unroll
    for (int o = 16; o; o >>= 1) s += __shfl_down_sync(0xffffffffu, s, o);
    if (lane == 0) *out = s;
}

// ---------------------------------------- GAT: fused exp + denom + scatter-add
// 16 threads per edge; one v4 red per thread (4x fewer L2 atomic ops).
__global__ void gat_scatter_k(const int* __restrict__ src, const int* __restrict__ dst,
                              const float* __restrict__ fsrc, int zidx) {
    int t = blockIdx.x * blockDim.x + threadIdx.x;
    int edge = t >> 4;
    if (edge >= EE) return;           // grid is exact; all lanes active
    int sub  = t & 15;
    int lane = threadIdx.x & 31;
    int si = __ldg(src + edge);
    int di = __ldg(dst + edge);
    float ex = 0.f;
    if (sub == 0) {
        float e = g_el[si] + g_er[di];
        e = e > 0.f ? e : 0.01f * e;          // leaky_relu
        ex = __expf(e);                       // softmax w/o max-shift (exact math)
        atomicAdd(g_s + di, ex);
    }
    ex = __shfl_sync(0xffffffffu, ex, lane & 16);
    float4 f = __ldg((const float4*)fsrc + (size_t)si * 16 + sub);
    float* zp = g_z + (size_t)zidx * ZSZ + (size_t)di * DD + sub * 4;
    asm volatile("red.global.add.v4.f32 [%0], {%1, %2, %3, %4};"
                 :: "l"(zp), "f"(ex * f.x), "f"(ex * f.y), "f"(ex * f.z), "f"(ex * f.w)
                 : "memory");
}

// ------------------------------------------------- GAT: divide by denom + ELU
__global__ void gat_final_k(int zidx) {
    int t = blockIdx.x * blockDim.x + threadIdx.x;
    if (t >= ZSZ) return;
    float sv = g_s[t >> 6];
    float* z = g_z + (size_t)zidx * ZSZ;
    float v = sv > 0.f ? z[t] / sv : 0.f;
    z[t] = v > 0.f ? v : expm1f(v);
}

// --------------------------------------------------------- GraphConv: degrees
__global__ void deg_k(const int* __restrict__ src, const int* __restrict__ dst) {
    int t = blockIdx.x * blockDim.x + threadIdx.x;
    if (t >= EE) return;
    atomicAdd(g_no + __ldg(src + t), 1.f);
    atomicAdd(g_ni + __ldg(dst + t), 1.f);
}

__global__ void norm_k() {
    int t = blockIdx.x * blockDim.x + threadIdx.x;
    if (t >= NU) return;
    float a = g_no[t]; g_no[t] = rsqrtf(a > 0.f ? a : 1.f);
    float b = g_ni[t]; g_ni[t] = rsqrtf(b > 0.f ? b : 1.f);
}

// -------------------------------------------------- GraphConv: scatter h[src]
__global__ void gc_scatter_k(const int* __restrict__ src, const int* __restrict__ dst,
                             const float* __restrict__ fsrc, int zidx) {
    int t = blockIdx.x * blockDim.x + threadIdx.x;
    int edge = t >> 4;
    if (edge >= EE) return;
    int sub = t & 15;
    int si = __ldg(src + edge);
    int di = __ldg(dst + edge);
    float c = g_no[si];
    float4 f = __ldg((const float4*)fsrc + (size_t)si * 16 + sub);
    float* zp = g_z + (size_t)zidx * ZSZ + (size_t)di * DD + sub * 4;
    asm volatile("red.global.add.v4.f32 [%0], {%1, %2, %3, %4};"
                 :: "l"(zp), "f"(c * f.x), "f"(c * f.y), "f"(c * f.z), "f"(c * f.w)
                 : "memory");
}

// ------------------------------------- GraphConv: ni-scale + 64x64 GEMM + ELU
__global__ void gc_gemm_k(int zidx, const float* __restrict__ W, const float* __restrict__ b) {
    __shared__ float Wsh[DD * DD];
    int t = threadIdx.x;
    #pragma unroll
    for (int i = t; i < DD * DD; i += 256) Wsh[i] = W[i];
    __syncthreads();
    int node = blockIdx.x * 8 + (t >> 5);      // 6250 blocks * 8 warps == 50000
    int lane = t & 31;
    float* z = g_z + (size_t)zidx * ZSZ + (size_t)node * DD;
    float c  = g_ni[node];
    float r0 = z[lane] * c, r1 = z[lane + 32] * c;
    float a0 = b[lane],     a1 = b[lane + 32];
    #pragma unroll
    for (int d = 0; d < 32; d++) {
        float v = __shfl_sync(0xffffffffu, r0, d);
        a0 += v * Wsh[d * DD + lane];
        a1 += v * Wsh[d * DD + lane + 32];
    }
    #pragma unroll
    for (int d = 0; d < 32; d++) {
        float v = __shfl_sync(0xffffffffu, r1, d);
        a0 += v * Wsh[(d + 32) * DD + lane];
        a1 += v * Wsh[(d + 32) * DD + lane + 32];
    }
    z[lane]      = a0 > 0.f ? a0 : expm1f(a0);
    z[lane + 32] = a1 > 0.f ? a1 : expm1f(a1);
}

// --------------------------------------------------- Semantic attention score
// Per thread: one node, BOTH meta-path rows (each W1 smem load feeds 2 FMAs).
__global__ void __launch_bounds__(256)
sa_score_k(int z0idx, int z1idx, const float* __restrict__ W1,
           const float* __restrict__ b1, const float* __restrict__ w2, int wsoff) {
    __shared__ float W1sh[DD * HH];
    __shared__ float b1sh[HH], w2sh[HH];
    __shared__ float red[2];
    int t = threadIdx.x;
    for (int i = t; i < DD * HH; i += 256) W1sh[i] = W1[i];
    if (t < HH) { b1sh[t] = b1[t]; w2sh[t] = w2[t]; }
    if (t < 2) red[t] = 0.f;
    __syncthreads();

    int node = blockIdx.x * 256 + t;
    float part0 = 0.f, part1 = 0.f;
    if (node < NU) {
        float4 za[16], zb[16];
        const float4* p0 = (const float4*)(g_z + (size_t)z0idx * ZSZ) + (size_t)node * 16;
        const float4* p1 = (const float4*)(g_z + (size_t)z1idx * ZSZ) + (size_t)node * 16;
        #pragma unroll
        for (int i = 0; i < 16; i++) { za[i] = __ldg(p0 + i); zb[i] = __ldg(p1 + i); }
        for (int h = 0; h < HH; h++) {
            float a0 = b1sh[h], a1 = b1sh[h];
            #pragma unroll
            for (int i = 0; i < 16; i++) {
                float w0 = W1sh[(4 * i + 0) * HH + h];
                float w1 = W1sh[(4 * i + 1) * HH + h];
                float w2v = W1sh[(4 * i + 2) * HH + h];
                float w3 = W1sh[(4 * i + 3) * HH + h];
                a0 += za[i].x * w0 + za[i].y * w1 + za[i].z * w2v + za[i].w * w3;
                a1 += zb[i].x * w0 + zb[i].y * w1 + zb[i].z * w2v + zb[i].w * w3;
            }
            float wv = w2sh[h];
            part0 += tanhf(a0) * wv;
            part1 += tanhf(a1) * wv;
        }
    }
    #pragma unroll
    for (int o = 16; o; o >>= 1) {
        part0 += __shfl_down_sync(0xffffffffu, part0, o);
        part1 += __shfl_down_sync(0xffffffffu, part1, o);
    }
    if ((t & 31) == 0) { atomicAdd(&red[0], part0); atomicAdd(&red[1], part1); }
    __syncthreads();
    if (t == 0) {
        atomicAdd(g_wsum + wsoff,     red[0]);
        atomicAdd(g_wsum + wsoff + 1, red[1]);
    }
}

// ----------------------------------------------------------------- betas (x4)
__global__ void beta_k() {
    #pragma unroll
    for (int g = 0; g < 4; g++) {
        float w0 = g_wsum[2 * g]     * (1.0f / NU);
        float w1 = g_wsum[2 * g + 1] * (1.0f / NU);
        float m = fmaxf(w0, w1);
        float e0 = __expf(w0 - m), e1 = __expf(w1 - m);
        float inv = 1.f / (e0 + e1);
        g_beta[2 * g] = e0 * inv;
        g_beta[2 * g + 1] = e1 * inv;
    }
}

// ------------------------------------------------------------- final combine
__global__ void combine_k(float* __restrict__ out) {
    int t = blockIdx.x * blockDim.x + threadIdx.x;
    const int NT4 = (NU + NI) * 16;
    if (t >= NT4) return;
    const float4* Z = (const float4*)g_z;
    const size_t P = ZSZ / 4;
    float4 r;
    if (t < NU * 16) {
        float b0 = g_beta[0], b1 = g_beta[1], b4 = g_beta[4], b5 = g_beta[5];
        float4 x0 = Z[t], x1 = Z[P + t], x4 = Z[4 * P + t], x5 = Z[5 * P + t];
        r.x = b0 * x0.x + b1 * x1.x + b4 * x4.x + b5 * x5.x;
        r.y = b0 * x0.y + b1 * x1.y + b4 * x4.y + b5 * x5.y;
        r.z = b0 * x0.z + b1 * x1.z + b4 * x4.z + b5 * x5.z;
        r.w = b0 * x0.w + b1 * x1.w + b4 * x4.w + b5 * x5.w;
    } else {
        size_t u = t - NU * 16;
        float b2 = g_beta[2], b3 = g_beta[3], b6 = g_beta[6], b7 = g_beta[7];
        float4 x2 = Z[2 * P + u], x3 = Z[3 * P + u], x6 = Z[6 * P + u], x7 = Z[7 * P + u];
        r.x = b2 * x2.x + b3 * x3.x + b6 * x6.x + b7 * x7.x;
        r.y = b2 * x2.y + b3 * x3.y + b6 * x6.y + b7 * x7.y;
        r.z = b2 * x2.z + b3 * x3.z + b6 * x6.z + b7 * x7.z;
        r.w = b2 * x2.w + b3 * x3.w + b6 * x6.w + b7 * x7.w;
    }
    ((float4*)out)[t] = r;
}

// ============================================================== host launcher
extern "C" void kernel_launch(void* const* d_in, const int* in_sizes, int n_in,
                              void* d_out, int out_size) {
    const float* feat_user = (const float*)d_in[0];
    const float* feat_item = (const float*)d_in[1];
    const float* attn_l    = (const float*)d_in[2];
    const float* attn_r    = (const float*)d_in[3];
    const float* W_gc      = (const float*)d_in[4];
    const float* b_gc      = (const float*)d_in[5];
    const float* sa_rel_W1 = (const float*)d_in[6];
    const float* sa_rel_b1 = (const float*)d_in[7];
    const float* sa_rel_w2 = (const float*)d_in[8];
    const float* sa_u_W1   = (const float*)d_in[9];
    const float* sa_u_b1   = (const float*)d_in[10];
    const float* sa_u_w2   = (const float*)d_in[11];
    const float* sa_i_W1   = (const float*)d_in[12];
    const float* sa_i_b1   = (const float*)d_in[13];
    const float* sa_i_w2   = (const float*)d_in[14];
    const int* rel_u_src   = (const int*)d_in[15];
    const int* rel_u_dst   = (const int*)d_in[16];
    const int* rel_i_src   = (const int*)d_in[17];
    const int* rel_i_dst   = (const int*)d_in[18];
    const int* mp_u_src    = (const int*)d_in[19];
    const int* mp_u_dst    = (const int*)d_in[20];
    const int* mp_i_src    = (const int*)d_in[21];
    const int* mp_i_dst    = (const int*)d_in[22];
    float* out = (float*)d_out;

    const int TB = 256;
    const int NODES_BLKS = (NU + TB - 1) / TB;        // 196
    const int ZB4_BLKS   = (ZSZ / 4) / TB;            // 3125 (exact)
    const int LER_BLKS   = (2 * NU * 32) / TB;        // 12500 (exact)
    const int EDGE_BLKS  = (EE * 16) / TB;            // 31250 (exact)
    const int ZF_BLKS    = (ZSZ + TB - 1) / TB;       // 12500
    const int DEG_BLKS   = (EE + TB - 1) / TB;        // 1954
    const int GEMM_BLKS  = NU / 8;                    // 6250 (exact)

    // ---- 4 HeCo-GAT relations ----
    struct GatCfg { const int* src; const int* dst; const float* fs; const float* fd; int arow; int zidx; };
    GatCfg G[4] = {
        { rel_u_src,      rel_u_dst,      feat_item, feat_user, 0, 0 },
        { rel_u_src + EE, rel_u_dst + EE, feat_item, feat_user, 1, 1 },
        { rel_i_src,      rel_i_dst,      feat_user, feat_item, 2, 2 },
        { rel_i_src + EE, rel_i_dst + EE, feat_user, feat_item, 3, 3 },
    };
    for (int r = 0; r < 4; r++) {
        zero_nodes_k<<<NODES_BLKS, TB>>>();
        zero_zbuf_k<<<ZB4_BLKS, TB>>>(G[r].zidx);
        ler_k<<<LER_BLKS, TB>>>(G[r].fs, G[r].fd, attn_l + G[r].arow * DD, attn_r + G[r].arow * DD);
        gat_scatter_k<<<EDGE_BLKS, TB>>>(G[r].src, G[r].dst, G[r].fs, G[r].zidx);
        gat_final_k<<<ZF_BLKS, TB>>>(G[r].zidx);
    }

    // ---- 4 GraphConvs ----
    struct GcCfg { const int* src; const int* dst; const float* f; int w; int zidx; };
    GcCfg C[4] = {
        { mp_u_src,      mp_u_dst,      feat_user, 0, 4 },
        { mp_u_src + EE, mp_u_dst + EE, feat_user, 1, 5 },
        { mp_i_src,      mp_i_dst,      feat_item, 2, 6 },
        { mp_i_src + EE, mp_i_dst + EE, feat_item, 3, 7 },
    };
    for (int g = 0; g < 4; g++) {
        zero_nodes_k<<<NODES_BLKS, TB>>>();
        zero_zbuf_k<<<ZB4_BLKS, TB>>>(C[g].zidx);
        deg_k<<<DEG_BLKS, TB>>>(C[g].src, C[g].dst);
        norm_k<<<NODES_BLKS, TB>>>();
        gc_scatter_k<<<EDGE_BLKS, TB>>>(C[g].src, C[g].dst, C[g].f, C[g].zidx);
        gc_gemm_k<<<GEMM_BLKS, TB>>>(C[g].zidx, W_gc + C[g].w * DD * DD, b_gc + C[g].w * DD);
    }

    // ---- semantic attention scores ----
    sa_score_k<<<NODES_BLKS, TB>>>(0, 1, sa_rel_W1, sa_rel_b1, sa_rel_w2, 0);
    sa_score_k<<<NODES_BLKS, TB>>>(2, 3, sa_rel_W1, sa_rel_b1, sa_rel_w2, 2);
    sa_score_k<<<NODES_BLKS, TB>>>(4, 5, sa_u_W1,   sa_u_b1,   sa_u_w2,   4);
    sa_score_k<<<NODES_BLKS, TB>>>(6, 7, sa_i_W1,   sa_i_b1,   sa_i_w2,   6);

    beta_k<<<1, 1>>>();
    combine_k<<<((NU + NI) * 16 + TB - 1) / TB, TB>>>(out);
}